// round 11
// baseline (speedup 1.0000x reference)
#include <cuda_runtime.h>
#include <cuda_bf16.h>
#include <cstdint>

// out[i] = cos(x[i]) * cos(params[(i % 1024) * 3])
// x: 8*8192*1024 fp32 = 256MB; params: [16,64,3].
//
// Bulk-read + direct-store variant: each CTA bulk-loads ONE 16KB tile
// (TMA, L2 evict_first), computes from smem, and writes straight to
// global with STG.128 streaming stores from all threads. 16.5KB smem
// -> 12 CTAs/SM resident; no tid0-serial store chain. grid=16384.
//
// Tile = 4096 floats = 4 channel-blocks of 1024 -> float4 channel group
// of (tid + i*256) within any tile == tid -> ry lives in 4 registers.

#define THREADS 256
#define TILE_BYTES 16384
#define TILE_F4    (TILE_BYTES / 16)   // 1024
#define PER_THREAD (TILE_F4 / THREADS) // 4

__device__ __forceinline__ uint32_t smem_u32(const void* p) {
    uint64_t t;
    asm("cvta.to.shared.u64 %0, %1;" : "=l"(t) : "l"(p));
    return (uint32_t)t;
}

__device__ __forceinline__ uint64_t mk_evict_first_policy() {
    uint64_t pol;
    asm("createpolicy.fractional.L2::evict_first.b64 %0, 1.0;" : "=l"(pol));
    return pol;
}

__device__ __forceinline__ void mbar_wait0(uint32_t mbar) {
    uint32_t done;
    asm volatile(
        "{\n\t.reg .pred p;\n\t"
        "mbarrier.try_wait.parity.acquire.cta.shared::cta.b64 p, [%1], 0;\n\t"
        "selp.b32 %0, 1, 0, p;\n\t}"
        : "=r"(done) : "r"(mbar) : "memory");
    if (!done) {
        asm volatile(
            "{\n\t.reg .pred P1;\n\t"
            "WL_%=:\n\t"
            "mbarrier.try_wait.parity.acquire.cta.shared::cta.b64 P1, [%0], 0, 0x989680;\n\t"
            "@P1 bra.uni WD_%=;\n\t"
            "bra.uni WL_%=;\n\t"
            "WD_%=:\n\t}"
            :: "r"(mbar) : "memory");
    }
}

__global__ __launch_bounds__(THREADS)
void qa_bulkstg_kernel(const float* __restrict__ x,
                       const float* __restrict__ params,
                       float* __restrict__ out)
{
    __shared__ __align__(128) float4 s_in[TILE_F4];
    __shared__ __align__(8) uint64_t mbar;

    const int tid = threadIdx.x;

    // Per-thread ry (channel group == tid within every tile).
    const int c = tid * 4;
    float4 r;
    r.x = cosf(params[(c + 0) * 3]);
    r.y = cosf(params[(c + 1) * 3]);
    r.z = cosf(params[(c + 2) * 3]);
    r.w = cosf(params[(c + 3) * 3]);

    const uint32_t mb = smem_u32(&mbar);
    const uint32_t sb = smem_u32(s_in);

    const float* gsrc = x + (size_t)blockIdx.x * (TILE_BYTES / 4);
    float4* gdst = (float4*)(out + (size_t)blockIdx.x * (TILE_BYTES / 4));

    if (tid == 0) {
        asm volatile("mbarrier.init.shared.b64 [%0], 1;" :: "r"(mb) : "memory");
    }
    __syncthreads();

    if (tid == 0) {
        const uint64_t pol = mk_evict_first_policy();
        asm volatile("mbarrier.arrive.expect_tx.shared.b64 _, [%0], %1;"
                     :: "r"(mb), "r"((uint32_t)TILE_BYTES) : "memory");
        asm volatile(
            "cp.async.bulk.shared::cta.global.mbarrier::complete_tx::bytes.L2::cache_hint "
            "[%0], [%1], %2, [%3], %4;"
            :: "r"(sb), "l"(gsrc), "r"((uint32_t)TILE_BYTES), "r"(mb), "l"(pol)
            : "memory");
    }

    mbar_wait0(mb);

#pragma unroll
    for (int i = 0; i < PER_THREAD; i++) {
        float4 v = s_in[tid + i * THREADS];
        float4 o;
        o.x = __cosf(v.x) * r.x;
        o.y = __cosf(v.y) * r.y;
        o.z = __cosf(v.z) * r.z;
        o.w = __cosf(v.w) * r.w;
        __stcs(&gdst[tid + i * THREADS], o);   // direct streaming store
    }
}

extern "C" void kernel_launch(void* const* d_in, const int* in_sizes, int n_in,
                              void* d_out, int out_size)
{
    const float* x      = (const float*)d_in[0];
    const float* params = (const float*)d_in[1];
    float* out          = (float*)d_out;

    int n = in_sizes[0];                 // 67,108,864
    int floats_per_cta = TILE_BYTES / 4; // 4096
    int nctas = n / floats_per_cta;      // 16384 (exact)

    qa_bulkstg_kernel<<<nctas, THREADS>>>(x, params, out);
}

// round 12
// speedup vs baseline: 1.0004x; 1.0004x over previous
#include <cuda_runtime.h>
#include <cuda_bf16.h>
#include <cstdint>

// out[i] = cos(x[i]) * cos(params[(i % 1024) * 3])
// x: 8*8192*1024 fp32 = 256MB; params: [16,64,3].
//
// Quad-buffered TMA bulk stream: each CTA owns FOUR consecutive 8KB
// tiles; all four bulk loads issued immediately; compute in-place in
// smem; bulk-store each tile as soon as it's ready (finer read/write
// interleave than 2x16KB). L2 evict_first both directions.
// grid=8192, 33KB smem -> 6 CTAs/SM.
//
// Tile = 2048 floats = 2 channel-blocks of 1024 -> float4 channel group
// of (tid + i*256) within any tile == tid -> ry lives in 4 registers.

#define THREADS 256
#define NTILES 4
#define TILE_BYTES 8192
#define TILE_F4    (TILE_BYTES / 16)   // 512
#define PER_THREAD (TILE_F4 / THREADS) // 2

__device__ __forceinline__ uint32_t smem_u32(const void* p) {
    uint64_t t;
    asm("cvta.to.shared.u64 %0, %1;" : "=l"(t) : "l"(p));
    return (uint32_t)t;
}

__device__ __forceinline__ uint64_t mk_evict_first_policy() {
    uint64_t pol;
    asm("createpolicy.fractional.L2::evict_first.b64 %0, 1.0;" : "=l"(pol));
    return pol;
}

__device__ __forceinline__ void mbar_wait0(uint32_t mbar) {
    uint32_t done;
    asm volatile(
        "{\n\t.reg .pred p;\n\t"
        "mbarrier.try_wait.parity.acquire.cta.shared::cta.b64 p, [%1], 0;\n\t"
        "selp.b32 %0, 1, 0, p;\n\t}"
        : "=r"(done) : "r"(mbar) : "memory");
    if (!done) {
        asm volatile(
            "{\n\t.reg .pred P1;\n\t"
            "WL_%=:\n\t"
            "mbarrier.try_wait.parity.acquire.cta.shared::cta.b64 P1, [%0], 0, 0x989680;\n\t"
            "@P1 bra.uni WD_%=;\n\t"
            "bra.uni WL_%=;\n\t"
            "WD_%=:\n\t}"
            :: "r"(mbar) : "memory");
    }
}

__global__ __launch_bounds__(THREADS)
void qa_bulk4_kernel(const float* __restrict__ x,
                     const float* __restrict__ params,
                     float* __restrict__ out)
{
    __shared__ __align__(128) float4 s_buf[NTILES][TILE_F4];
    __shared__ __align__(8) uint64_t mbar[NTILES];

    const int tid = threadIdx.x;

    // Per-thread ry (channel group == tid within every tile).
    const int c = tid * 4;
    float4 r;
    r.x = cosf(params[(c + 0) * 3]);
    r.y = cosf(params[(c + 1) * 3]);
    r.z = cosf(params[(c + 2) * 3]);
    r.w = cosf(params[(c + 3) * 3]);

    uint32_t mb[NTILES], sb[NTILES];
#pragma unroll
    for (int t = 0; t < NTILES; t++) {
        mb[t] = smem_u32(&mbar[t]);
        sb[t] = smem_u32(s_buf[t]);
    }

    const float* gsrc = x   + (size_t)blockIdx.x * NTILES * (TILE_BYTES / 4);
    float*       gdst = out + (size_t)blockIdx.x * NTILES * (TILE_BYTES / 4);

    if (tid == 0) {
#pragma unroll
        for (int t = 0; t < NTILES; t++)
            asm volatile("mbarrier.init.shared.b64 [%0], 1;" :: "r"(mb[t]) : "memory");
    }
    __syncthreads();

    if (tid == 0) {
        const uint64_t pol = mk_evict_first_policy();
        // Issue ALL four bulk loads immediately.
#pragma unroll
        for (int t = 0; t < NTILES; t++) {
            asm volatile("mbarrier.arrive.expect_tx.shared.b64 _, [%0], %1;"
                         :: "r"(mb[t]), "r"((uint32_t)TILE_BYTES) : "memory");
            asm volatile(
                "cp.async.bulk.shared::cta.global.mbarrier::complete_tx::bytes.L2::cache_hint "
                "[%0], [%1], %2, [%3], %4;"
                :: "r"(sb[t]), "l"(gsrc + t * (TILE_BYTES / 4)),
                   "r"((uint32_t)TILE_BYTES), "r"(mb[t]), "l"(pol)
                : "memory");
        }
    }

#pragma unroll
    for (int t = 0; t < NTILES; t++) {
        mbar_wait0(mb[t]);
#pragma unroll
        for (int i = 0; i < PER_THREAD; i++) {
            float4 v = s_buf[t][tid + i * THREADS];
            float4 o;
            o.x = __cosf(v.x) * r.x;
            o.y = __cosf(v.y) * r.y;
            o.z = __cosf(v.z) * r.z;
            o.w = __cosf(v.w) * r.w;
            s_buf[t][tid + i * THREADS] = o;   // in-place
        }
        __syncthreads();
        if (tid == 0) {
            const uint64_t pol = mk_evict_first_policy();
            asm volatile("fence.proxy.async.shared::cta;" ::: "memory");
            asm volatile(
                "cp.async.bulk.global.shared::cta.bulk_group.L2::cache_hint "
                "[%0], [%1], %2, %3;"
                :: "l"(gdst + t * (TILE_BYTES / 4)), "r"(sb[t]),
                   "r"((uint32_t)TILE_BYTES), "l"(pol)
                : "memory");
            asm volatile("cp.async.bulk.commit_group;" ::: "memory");
        }
    }

    // smem must stay live until all stores have read it.
    if (tid == 0)
        asm volatile("cp.async.bulk.wait_group.read 0;" ::: "memory");
}

extern "C" void kernel_launch(void* const* d_in, const int* in_sizes, int n_in,
                              void* d_out, int out_size)
{
    const float* x      = (const float*)d_in[0];
    const float* params = (const float*)d_in[1];
    float* out          = (float*)d_out;

    int n = in_sizes[0];                            // 67,108,864
    int floats_per_cta = NTILES * TILE_BYTES / 4;   // 8192
    int nctas = n / floats_per_cta;                 // 8192 (exact)

    qa_bulk4_kernel<<<nctas, THREADS>>>(x, params, out);
}